// round 2
// baseline (speedup 1.0000x reference)
#include <cuda_runtime.h>
#include <math.h>

#define D   128
#define HC  128
#define TD  32
#define MD  64
#define AD  96   // TD + MD
#define NMAX 50048

// scratch (static device memory — no allocations allowed)
__device__ float g_q[NMAX * HC];
__device__ float g_k[NMAX * HC];
__device__ float g_v[NMAX * HC];
__device__ float g_sk[NMAX * HC];
__device__ float g_den[NMAX * 2];

// ---------------------------------------------------------------------------
// K0: zero the output accumulator and the softmax denominators
// ---------------------------------------------------------------------------
__global__ void init_kernel(float* __restrict__ out, int n) {
    int i = blockIdx.x * blockDim.x + threadIdx.x;
    if (i < n * HC) out[i] = 0.0f;
    if (i < n * 2)  g_den[i] = 0.0f;
}

// ---------------------------------------------------------------------------
// K1: fused node projections  q/k/v/skip = x @ W + b
// block = 128 threads (one per output column), 8 rows per block
// ---------------------------------------------------------------------------
__global__ __launch_bounds__(128) void proj_kernel(
    const float* __restrict__ x,
    const float* __restrict__ Wq, const float* __restrict__ bq,
    const float* __restrict__ Wk, const float* __restrict__ bk,
    const float* __restrict__ Wv, const float* __restrict__ bv,
    const float* __restrict__ Ws, const float* __restrict__ bs,
    int n)
{
    __shared__ __align__(16) float xs[8][D];
    const int r0 = blockIdx.x * 8;
    const int c  = threadIdx.x;

    #pragma unroll
    for (int r = 0; r < 8; r++)
        xs[r][c] = (r0 + r < n) ? x[(size_t)(r0 + r) * D + c] : 0.0f;
    __syncthreads();

    float aq[8] = {}, ak[8] = {}, av[8] = {}, aw[8] = {};
    #pragma unroll 4
    for (int k = 0; k < D; k++) {
        const float wq = Wq[k * HC + c];
        const float wk = Wk[k * HC + c];
        const float wv = Wv[k * HC + c];
        const float ws = Ws[k * HC + c];
        #pragma unroll
        for (int r = 0; r < 8; r++) {
            const float xv = xs[r][k];
            aq[r] += xv * wq;
            ak[r] += xv * wk;
            av[r] += xv * wv;
            aw[r] += xv * ws;
        }
    }
    #pragma unroll
    for (int r = 0; r < 8; r++) {
        const int row = r0 + r;
        if (row < n) {
            g_q[row * HC + c]  = aq[r] + bq[c];
            g_k[row * HC + c]  = ak[r] + bk[c];
            g_v[row * HC + c]  = av[r] + bv[c];
            g_sk[row * HC + c] = aw[r] + bs[c];
        }
    }
}

// ---------------------------------------------------------------------------
// K2: per-edge kernel.
//   edge_attr = [cos(t*Wt+bt), msg]  (96)
//   e = edge_attr @ We               (128, We column held in registers)
//   alpha_h = dot(q[dst], k[src]+e) / 8   per head (64 channels each)
//   w = exp(alpha)  (max-subtraction cancels analytically; alpha is O(1))
//   atomic: out[dst] += w*(v[src]+e) ; den[dst,h] += w
// block = 128 threads (one per channel), grid-stride over edges
// NOTE: edge_index / edge_time are int32 on device (JAX x64 disabled).
// ---------------------------------------------------------------------------
__global__ __launch_bounds__(128) void edge_kernel(
    const int* __restrict__ ei,   // [2, E]  int32
    const int* __restrict__ et,   // [E]     int32
    const float* __restrict__ msg,      // [E, 64]
    const float* __restrict__ Wt, const float* __restrict__ bt,
    const float* __restrict__ We,       // [96, 128]
    float* __restrict__ out, int E)
{
    __shared__ __align__(16) float attr_s[AD];
    __shared__ float red_s[4];
    __shared__ int sd_s[2];

    const int tid  = threadIdx.x;
    const int warp = tid >> 5;
    const int lane = tid & 31;
    const int head = tid >> 6;

    // stage this thread's We column in registers (96 regs)
    float wreg[AD];
    #pragma unroll
    for (int j = 0; j < AD; j++) wreg[j] = We[j * HC + tid];

    float wtv = 0.0f, btv = 0.0f;
    if (tid < TD) { wtv = Wt[tid]; btv = bt[tid]; }

    for (int e = blockIdx.x; e < E; e += gridDim.x) {
        // stage edge attributes
        if (tid < TD) {
            const float t = (float)et[e];
            attr_s[tid] = cosf(t * wtv + btv);
        } else if (tid < AD) {
            attr_s[tid] = msg[(size_t)e * MD + (tid - TD)];
        }
        if (tid == 0) { sd_s[0] = ei[e]; sd_s[1] = ei[E + e]; }
        __syncthreads();

        const int src = sd_s[0];
        const int dst = sd_s[1];

        // e_c = attr . We[:, c]   (vectorized LDS.128 broadcast of attr)
        float ec = 0.0f;
        const float4* a4 = (const float4*)attr_s;
        #pragma unroll
        for (int j = 0; j < AD / 4; j++) {
            const float4 a = a4[j];
            ec += a.x * wreg[4 * j + 0];
            ec += a.y * wreg[4 * j + 1];
            ec += a.z * wreg[4 * j + 2];
            ec += a.w * wreg[4 * j + 3];
        }

        const float qv = g_q[(size_t)dst * HC + tid];
        const float kv = g_k[(size_t)src * HC + tid];
        const float vv = g_v[(size_t)src * HC + tid];

        // per-head dot product: reduce over 64 channels = 2 warps
        float p = qv * (kv + ec);
        #pragma unroll
        for (int off = 16; off; off >>= 1)
            p += __shfl_xor_sync(0xffffffffu, p, off);
        if (lane == 0) red_s[warp] = p;
        __syncthreads();

        const float alpha = 0.125f * (red_s[2 * head] + red_s[2 * head + 1]);
        const float w = expf(alpha);

        atomicAdd(&out[(size_t)dst * HC + tid], w * (vv + ec));
        if (lane == 0 && (warp & 1) == 0)
            atomicAdd(&g_den[dst * 2 + head], w);
        // smem reuse across iterations is ordered by the two barriers above
    }
}

// ---------------------------------------------------------------------------
// K3: out = out / (den + 1e-16) + skip
// ---------------------------------------------------------------------------
__global__ void final_kernel(float* __restrict__ out, int n) {
    int i = blockIdx.x * blockDim.x + threadIdx.x;
    if (i >= n * HC) return;
    const int row  = i >> 7;
    const int head = (i >> 6) & 1;
    out[i] = out[i] / (g_den[row * 2 + head] + 1e-16f) + g_sk[i];
}

// ---------------------------------------------------------------------------
extern "C" void kernel_launch(void* const* d_in, const int* in_sizes, int n_in,
                              void* d_out, int out_size)
{
    const float* x   = (const float*)d_in[0];
    const int*   ei  = (const int*)d_in[1];
    const int*   et  = (const int*)d_in[2];
    const float* msg = (const float*)d_in[3];
    const float* Wt  = (const float*)d_in[4];
    const float* bt  = (const float*)d_in[5];
    const float* Wq  = (const float*)d_in[6];
    const float* bq  = (const float*)d_in[7];
    const float* Wk  = (const float*)d_in[8];
    const float* bk  = (const float*)d_in[9];
    const float* Wv  = (const float*)d_in[10];
    const float* bv  = (const float*)d_in[11];
    const float* We  = (const float*)d_in[12];
    const float* Ws  = (const float*)d_in[13];
    const float* bs  = (const float*)d_in[14];
    float* out = (float*)d_out;

    const int N = in_sizes[0] / D;
    const int E = in_sizes[2];

    init_kernel<<<(N * HC + 255) / 256, 256>>>(out, N);
    proj_kernel<<<(N + 7) / 8, 128>>>(x, Wq, bq, Wk, bk, Wv, bv, Ws, bs, N);
    edge_kernel<<<1184, 128>>>(ei, et, msg, Wt, bt, We, out, E);
    final_kernel<<<(N * HC + 255) / 256, 256>>>(out, N);
}

// round 3
// speedup vs baseline: 1.1041x; 1.1041x over previous
#include <cuda_runtime.h>
#include <math.h>

#define D   128
#define HC  128
#define TD  32
#define MD  64
#define AD  96   // TD + MD
#define NMAX 50048
#define EPI 4    // edges per block iteration

// scratch (static device memory — no allocations allowed)
__device__ float g_q[NMAX * HC];
__device__ float g_k[NMAX * HC];
__device__ float g_v[NMAX * HC];
__device__ float g_sk[NMAX * HC];
__device__ float g_den[NMAX * 2];

__device__ __forceinline__ void red_add_v4(float* addr, float4 v) {
    asm volatile("red.global.add.v4.f32 [%0], {%1,%2,%3,%4};"
                 :: "l"(addr), "f"(v.x), "f"(v.y), "f"(v.z), "f"(v.w)
                 : "memory");
}

// ---------------------------------------------------------------------------
// K0: zero the output accumulator and the softmax denominators
// ---------------------------------------------------------------------------
__global__ void init_kernel(float* __restrict__ out, int n) {
    int i = blockIdx.x * blockDim.x + threadIdx.x;
    if (i < n * HC) out[i] = 0.0f;
    if (i < n * 2)  g_den[i] = 0.0f;
}

// ---------------------------------------------------------------------------
// K1: fused node projections  q/k/v/skip = x @ W + b
// block = 128 threads (one per output column), 16 rows per block
// ---------------------------------------------------------------------------
__global__ __launch_bounds__(128) void proj_kernel(
    const float* __restrict__ x,
    const float* __restrict__ Wq, const float* __restrict__ bq,
    const float* __restrict__ Wk, const float* __restrict__ bk,
    const float* __restrict__ Wv, const float* __restrict__ bv,
    const float* __restrict__ Ws, const float* __restrict__ bs,
    int n)
{
    __shared__ __align__(16) float xs[16][D];
    const int r0 = blockIdx.x * 16;
    const int c  = threadIdx.x;

    #pragma unroll
    for (int r = 0; r < 16; r++)
        xs[r][c] = (r0 + r < n) ? x[(size_t)(r0 + r) * D + c] : 0.0f;
    __syncthreads();

    float aq[16] = {}, ak[16] = {}, av[16] = {}, aw[16] = {};
    #pragma unroll 2
    for (int k = 0; k < D; k++) {
        const float wq = Wq[k * HC + c];
        const float wk = Wk[k * HC + c];
        const float wv = Wv[k * HC + c];
        const float ws = Ws[k * HC + c];
        #pragma unroll
        for (int r = 0; r < 16; r++) {
            const float xv = xs[r][k];
            aq[r] += xv * wq;
            ak[r] += xv * wk;
            av[r] += xv * wv;
            aw[r] += xv * ws;
        }
    }
    #pragma unroll
    for (int r = 0; r < 16; r++) {
        const int row = r0 + r;
        if (row < n) {
            g_q[(size_t)row * HC + c]  = aq[r] + bq[c];
            g_k[(size_t)row * HC + c]  = ak[r] + bk[c];
            g_v[(size_t)row * HC + c]  = av[r] + bv[c];
            g_sk[(size_t)row * HC + c] = aw[r] + bs[c];
        }
    }
}

// ---------------------------------------------------------------------------
// K2: per-edge kernel, 4 edges per block iteration.
//   edge_attr = [cos(t*Wt+bt), msg]  (96)
//   e = edge_attr @ We               (We column held in registers, 96 regs)
//   alpha_h = dot(q[dst], k[src]+e) / 8
//   w = exp(alpha)  (max-subtraction cancels analytically)
//   scatter: red.v4 of w*(v[src]+e) into out; scalar red for denominators
// ---------------------------------------------------------------------------
__global__ __launch_bounds__(128, 3) void edge_kernel(
    const int* __restrict__ ei,     // [2, E] int32
    const int* __restrict__ et,     // [E]    int32
    const float* __restrict__ msg,  // [E, 64]
    const float* __restrict__ Wt, const float* __restrict__ bt,
    const float* __restrict__ We,   // [96, 128]
    float* __restrict__ out, int E)
{
    __shared__ __align__(16) float attr_s[EPI][AD];
    __shared__ __align__(16) float out_s[EPI][HC];
    __shared__ float red_s[EPI][4];
    __shared__ int   sd_s[2][EPI];
    __shared__ float wt_s[TD], bt_s[TD];

    const int tid  = threadIdx.x;
    const int warp = tid >> 5;
    const int lane = tid & 31;
    const int head = tid >> 6;

    // stage this thread's We column in registers (96 regs)
    float wreg[AD];
    #pragma unroll
    for (int j = 0; j < AD; j++) wreg[j] = We[j * HC + tid];

    if (tid < TD) { wt_s[tid] = Wt[tid]; bt_s[tid] = bt[tid]; }
    __syncthreads();

    const int stride = gridDim.x * EPI;
    for (int e0 = blockIdx.x * EPI; e0 < E; e0 += stride) {
        const int nE = min(EPI, E - e0);

        // ---- stage edge attributes + indices ----
        #pragma unroll
        for (int ee = 0; ee < EPI; ee++) {
            if (ee < nE && tid < AD) {
                const int e = e0 + ee;
                float v;
                if (tid < TD) v = cosf((float)et[e] * wt_s[tid] + bt_s[tid]);
                else          v = msg[(size_t)e * MD + (tid - TD)];
                attr_s[ee][tid] = v;
            }
        }
        if (tid < nE) { sd_s[0][tid] = ei[e0 + tid]; sd_s[1][tid] = ei[E + e0 + tid]; }
        __syncthreads();   // BAR A

        // ---- gather q/k/v for all edges (batched loads, MLP=12) ----
        int srcI[EPI], dstI[EPI];
        float qv[EPI], kv[EPI], vv[EPI];
        #pragma unroll
        for (int ee = 0; ee < EPI; ee++) {
            srcI[ee] = (ee < nE) ? sd_s[0][ee] : 0;
            dstI[ee] = (ee < nE) ? sd_s[1][ee] : 0;
        }
        #pragma unroll
        for (int ee = 0; ee < EPI; ee++) {
            qv[ee] = g_q[(size_t)dstI[ee] * HC + tid];
            kv[ee] = g_k[(size_t)srcI[ee] * HC + tid];
            vv[ee] = g_v[(size_t)srcI[ee] * HC + tid];
        }

        // ---- e-channel GEMM: ec[ee] = attr[ee] . We[:, tid] ----
        float ec[EPI];
        #pragma unroll
        for (int ee = 0; ee < EPI; ee++) {
            float s0 = 0.0f, s1 = 0.0f;
            const float4* a4 = (const float4*)attr_s[ee];
            #pragma unroll
            for (int j = 0; j < AD / 8; j++) {
                const float4 a = a4[2 * j];
                const float4 b = a4[2 * j + 1];
                s0 += a.x * wreg[8 * j + 0];
                s1 += a.y * wreg[8 * j + 1];
                s0 += a.z * wreg[8 * j + 2];
                s1 += a.w * wreg[8 * j + 3];
                s0 += b.x * wreg[8 * j + 4];
                s1 += b.y * wreg[8 * j + 5];
                s0 += b.z * wreg[8 * j + 6];
                s1 += b.w * wreg[8 * j + 7];
            }
            ec[ee] = s0 + s1;
        }

        // ---- per-head attention logits ----
        #pragma unroll
        for (int ee = 0; ee < EPI; ee++) {
            float p = qv[ee] * (kv[ee] + ec[ee]);
            #pragma unroll
            for (int off = 16; off; off >>= 1)
                p += __shfl_xor_sync(0xffffffffu, p, off);
            if (lane == 0) red_s[ee][warp] = p;
        }
        __syncthreads();   // BAR B

        float wgt[EPI];
        #pragma unroll
        for (int ee = 0; ee < EPI; ee++) {
            const float alpha = 0.125f * (red_s[ee][2 * head] + red_s[ee][2 * head + 1]);
            wgt[ee] = __expf(alpha);
            out_s[ee][tid] = wgt[ee] * (vv[ee] + ec[ee]);
        }
        // denominator atomics: thread 0 -> head 0, thread 64 -> head 1
        if (lane == 0 && (warp & 1) == 0) {
            #pragma unroll
            for (int ee = 0; ee < EPI; ee++)
                if (ee < nE) atomicAdd(&g_den[dstI[ee] * 2 + head], wgt[ee]);
        }
        __syncthreads();   // BAR C

        // ---- vectorized scatter: one RED.128 per thread ----
        {
            const int ee = tid >> 5;       // edge slot
            const int c4 = lane * 4;       // 4 consecutive channels
            if (ee < nE) {
                const float4 val = *(const float4*)&out_s[ee][c4];
                red_add_v4(&out[(size_t)dstI[ee] * HC + c4], val);
            }
        }
        // next iteration's writes touch attr_s/sd_s only; out_s/red_s reads
        // complete before BAR A of the next pass (every thread re-syncs there)
    }
}

// ---------------------------------------------------------------------------
// K3: out = out / (den + 1e-16) + skip
// ---------------------------------------------------------------------------
__global__ void final_kernel(float* __restrict__ out, int n) {
    int i = blockIdx.x * blockDim.x + threadIdx.x;
    if (i >= n * HC) return;
    const int row  = i >> 7;
    const int head = (i >> 6) & 1;
    out[i] = out[i] / (g_den[row * 2 + head] + 1e-16f) + g_sk[i];
}

// ---------------------------------------------------------------------------
extern "C" void kernel_launch(void* const* d_in, const int* in_sizes, int n_in,
                              void* d_out, int out_size)
{
    const float* x   = (const float*)d_in[0];
    const int*   ei  = (const int*)d_in[1];
    const int*   et  = (const int*)d_in[2];
    const float* msg = (const float*)d_in[3];
    const float* Wt  = (const float*)d_in[4];
    const float* bt  = (const float*)d_in[5];
    const float* Wq  = (const float*)d_in[6];
    const float* bq  = (const float*)d_in[7];
    const float* Wk  = (const float*)d_in[8];
    const float* bk  = (const float*)d_in[9];
    const float* Wv  = (const float*)d_in[10];
    const float* bv  = (const float*)d_in[11];
    const float* We  = (const float*)d_in[12];
    const float* Ws  = (const float*)d_in[13];
    const float* bs  = (const float*)d_in[14];
    float* out = (float*)d_out;

    const int N = in_sizes[0] / D;
    const int E = in_sizes[2];

    init_kernel<<<(N * HC + 255) / 256, 256>>>(out, N);
    proj_kernel<<<(N + 15) / 16, 128>>>(x, Wq, bq, Wk, bk, Wv, bv, Ws, bs, N);
    edge_kernel<<<444, 128>>>(ei, et, msg, Wt, bt, We, out, E);
    final_kernel<<<(N * HC + 255) / 256, 256>>>(out, N);
}

// round 4
// speedup vs baseline: 1.1840x; 1.0724x over previous
#include <cuda_runtime.h>
#include <math.h>

#define D   128
#define HC  128
#define TD  32
#define MD  64
#define AD  96   // TD + MD
#define NMAX 50048
#define EPI 4    // edges per block iteration (2 packed pairs)

// scratch (static device memory — no allocations allowed)
__device__ float g_q[NMAX * HC];
__device__ float g_k[NMAX * HC];
__device__ float g_v[NMAX * HC];
__device__ float g_sk[NMAX * HC];
__device__ float g_den[NMAX * 2];

typedef unsigned long long ull;

__device__ __forceinline__ ull pack2(float lo, float hi) {
    ull r;
    asm("mov.b64 %0, {%1, %2};" : "=l"(r) : "f"(lo), "f"(hi));
    return r;
}
__device__ __forceinline__ void unpack2(ull v, float& lo, float& hi) {
    asm("mov.b64 {%0, %1}, %2;" : "=f"(lo), "=f"(hi) : "l"(v));
}
__device__ __forceinline__ ull ffma2(ull a, ull b, ull c) {
    ull d;
    asm("fma.rn.f32x2 %0, %1, %2, %3;" : "=l"(d) : "l"(a), "l"(b), "l"(c));
    return d;
}
__device__ __forceinline__ ull fadd2(ull a, ull b) {
    ull d;
    asm("add.rn.f32x2 %0, %1, %2;" : "=l"(d) : "l"(a), "l"(b));
    return d;
}
__device__ __forceinline__ void red_add_v4(float* addr, float4 v) {
    asm volatile("red.global.add.v4.f32 [%0], {%1,%2,%3,%4};"
                 :: "l"(addr), "f"(v.x), "f"(v.y), "f"(v.z), "f"(v.w)
                 : "memory");
}

// ---------------------------------------------------------------------------
// K0: zero the output accumulator and the softmax denominators
// ---------------------------------------------------------------------------
__global__ void init_kernel(float* __restrict__ out, int n) {
    int i = blockIdx.x * blockDim.x + threadIdx.x;
    if (i < n * HC) out[i] = 0.0f;
    if (i < n * 2)  g_den[i] = 0.0f;
}

// ---------------------------------------------------------------------------
// K1: fused node projections  q/k/v/skip = x @ W + b
// block = 128 threads (one per output column), 16 rows per block,
// rows processed as 8 packed f32x2 pairs.
// ---------------------------------------------------------------------------
__global__ __launch_bounds__(128) void proj_kernel(
    const float* __restrict__ x,
    const float* __restrict__ Wq, const float* __restrict__ bq,
    const float* __restrict__ Wk, const float* __restrict__ bk,
    const float* __restrict__ Wv, const float* __restrict__ bv,
    const float* __restrict__ Ws, const float* __restrict__ bs,
    int n)
{
    // xs2[k][r2] = {x[2*r2][k], x[2*r2+1][k]}, padded to 9 pairs (bank decorrelation)
    __shared__ __align__(16) float2 xs2[D][9];
    const int r0 = blockIdx.x * 16;
    const int c  = threadIdx.x;

    #pragma unroll
    for (int r = 0; r < 16; r++) {
        const int row = r0 + r;
        const float v = (row < n) ? x[(size_t)row * D + c] : 0.0f;
        ((float*)&xs2[c][r >> 1])[r & 1] = v;
    }
    __syncthreads();

    ull aq[8], ak[8], av[8], aw[8];
    #pragma unroll
    for (int r = 0; r < 8; r++) { aq[r] = 0; ak[r] = 0; av[r] = 0; aw[r] = 0; }

    #pragma unroll 2
    for (int k = 0; k < D; k++) {
        const float wq = Wq[k * HC + c];
        const float wk = Wk[k * HC + c];
        const float wv = Wv[k * HC + c];
        const float ws = Ws[k * HC + c];
        const ull wq2 = pack2(wq, wq);
        const ull wk2 = pack2(wk, wk);
        const ull wv2 = pack2(wv, wv);
        const ull ws2 = pack2(ws, ws);
        #pragma unroll
        for (int r = 0; r < 8; r++) {
            const ull xv2 = *(const ull*)&xs2[k][r];   // LDS.64 broadcast
            aq[r] = ffma2(xv2, wq2, aq[r]);
            ak[r] = ffma2(xv2, wk2, ak[r]);
            av[r] = ffma2(xv2, wv2, av[r]);
            aw[r] = ffma2(xv2, ws2, aw[r]);
        }
    }

    const float bqv = bq[c], bkv = bk[c], bvv = bv[c], bsv = bs[c];
    #pragma unroll
    for (int r = 0; r < 8; r++) {
        float lo, hi;
        const int rowL = r0 + 2 * r, rowH = rowL + 1;
        unpack2(aq[r], lo, hi);
        if (rowL < n) g_q[(size_t)rowL * HC + c] = lo + bqv;
        if (rowH < n) g_q[(size_t)rowH * HC + c] = hi + bqv;
        unpack2(ak[r], lo, hi);
        if (rowL < n) g_k[(size_t)rowL * HC + c] = lo + bkv;
        if (rowH < n) g_k[(size_t)rowH * HC + c] = hi + bkv;
        unpack2(av[r], lo, hi);
        if (rowL < n) g_v[(size_t)rowL * HC + c] = lo + bvv;
        if (rowH < n) g_v[(size_t)rowH * HC + c] = hi + bvv;
        unpack2(aw[r], lo, hi);
        if (rowL < n) g_sk[(size_t)rowL * HC + c] = lo + bsv;
        if (rowH < n) g_sk[(size_t)rowH * HC + c] = hi + bsv;
    }
}

// ---------------------------------------------------------------------------
// K2: per-edge kernel, 4 edges per block iteration, edge-pair-packed f32x2.
//   edge_attr = [cos(t*Wt+bt), msg]  (96)
//   e = edge_attr @ We               (We column held in registers)
//   alpha_h = dot(q[dst], k[src]+e) / 8
//   w = exp(alpha)  (max-subtraction cancels analytically)
//   scatter: red.v4 of w*(v[src]+e) into out; scalar red for denominators
// ---------------------------------------------------------------------------
__global__ __launch_bounds__(128, 3) void edge_kernel(
    const int* __restrict__ ei,     // [2, E] int32
    const int* __restrict__ et,     // [E]    int32
    const float* __restrict__ msg,  // [E, 64]
    const float* __restrict__ Wt, const float* __restrict__ bt,
    const float* __restrict__ We,   // [96, 128]
    float* __restrict__ out, int E)
{
    // attr packed by edge pair: attr2f[p][j][sub] = attr[2p+sub][j]
    __shared__ __align__(16) float attr2f[2][AD][2];
    __shared__ __align__(16) float out_s[EPI][HC];
    __shared__ float red_s[EPI][4];
    __shared__ int   sd_s[2][EPI];
    __shared__ float wt_s[TD], bt_s[TD];

    const int tid  = threadIdx.x;
    const int warp = tid >> 5;
    const int lane = tid & 31;
    const int head = tid >> 6;

    // stage this thread's We column in registers (96 regs)
    float wreg[AD];
    #pragma unroll
    for (int j = 0; j < AD; j++) wreg[j] = We[j * HC + tid];

    if (tid < TD) { wt_s[tid] = Wt[tid]; bt_s[tid] = bt[tid]; }
    __syncthreads();

    const int stride = gridDim.x * EPI;
    for (int e0 = blockIdx.x * EPI; e0 < E; e0 += stride) {
        const int nE = min(EPI, E - e0);

        // ---- stage edge attributes (interleaved by pair) + indices ----
        #pragma unroll
        for (int ee = 0; ee < EPI; ee++) {
            if (ee < nE && tid < AD) {
                const int e = e0 + ee;
                float v;
                if (tid < TD) v = cosf((float)et[e] * wt_s[tid] + bt_s[tid]);
                else          v = msg[(size_t)e * MD + (tid - TD)];
                attr2f[ee >> 1][tid][ee & 1] = v;
            }
        }
        if (tid < nE) { sd_s[0][tid] = ei[e0 + tid]; sd_s[1][tid] = ei[E + e0 + tid]; }
        __syncthreads();   // BAR A

        // ---- gather q/k/v for all edges (batched loads) ----
        int srcI[EPI], dstI[EPI];
        float qv[EPI], kv[EPI], vv[EPI];
        #pragma unroll
        for (int ee = 0; ee < EPI; ee++) {
            srcI[ee] = (ee < nE) ? sd_s[0][ee] : 0;
            dstI[ee] = (ee < nE) ? sd_s[1][ee] : 0;
        }
        #pragma unroll
        for (int ee = 0; ee < EPI; ee++) {
            qv[ee] = g_q[(size_t)dstI[ee] * HC + tid];
            kv[ee] = g_k[(size_t)srcI[ee] * HC + tid];
            vv[ee] = g_v[(size_t)srcI[ee] * HC + tid];
        }

        // ---- e-channel GEMM, f32x2-packed over edge pairs ----
        // accE/accO: even/odd-j accumulator per pair (4 independent chains)
        ull accE0 = 0, accO0 = 0, accE1 = 0, accO1 = 0;
        {
            const ulonglong2* a0 = (const ulonglong2*)&attr2f[0][0][0];
            const ulonglong2* a1 = (const ulonglong2*)&attr2f[1][0][0];
            #pragma unroll
            for (int j2 = 0; j2 < AD / 2; j2++) {
                const ull w0 = pack2(wreg[2 * j2],     wreg[2 * j2]);
                const ull w1 = pack2(wreg[2 * j2 + 1], wreg[2 * j2 + 1]);
                const ulonglong2 p0 = a0[j2];   // LDS.128 broadcast
                const ulonglong2 p1 = a1[j2];
                accE0 = ffma2(p0.x, w0, accE0);
                accO0 = ffma2(p0.y, w1, accO0);
                accE1 = ffma2(p1.x, w0, accE1);
                accO1 = ffma2(p1.y, w1, accO1);
            }
        }
        float ec[EPI];
        unpack2(fadd2(accE0, accO0), ec[0], ec[1]);
        unpack2(fadd2(accE1, accO1), ec[2], ec[3]);

        // ---- per-head attention logits ----
        #pragma unroll
        for (int ee = 0; ee < EPI; ee++) {
            float p = qv[ee] * (kv[ee] + ec[ee]);
            #pragma unroll
            for (int off = 16; off; off >>= 1)
                p += __shfl_xor_sync(0xffffffffu, p, off);
            if (lane == 0) red_s[ee][warp] = p;
        }
        __syncthreads();   // BAR B

        float wgt[EPI];
        #pragma unroll
        for (int ee = 0; ee < EPI; ee++) {
            const float alpha = 0.125f * (red_s[ee][2 * head] + red_s[ee][2 * head + 1]);
            wgt[ee] = __expf(alpha);
            out_s[ee][tid] = wgt[ee] * (vv[ee] + ec[ee]);
        }
        // denominator atomics: thread 0 -> head 0, thread 64 -> head 1
        if (lane == 0 && (warp & 1) == 0) {
            #pragma unroll
            for (int ee = 0; ee < EPI; ee++)
                if (ee < nE) atomicAdd(&g_den[dstI[ee] * 2 + head], wgt[ee]);
        }
        __syncthreads();   // BAR C

        // ---- vectorized scatter: one RED.128 per thread ----
        {
            const int ee = tid >> 5;       // edge slot
            const int c4 = lane * 4;       // 4 consecutive channels
            if (ee < nE) {
                const float4 val = *(const float4*)&out_s[ee][c4];
                red_add_v4(&out[(size_t)dstI[ee] * HC + c4], val);
            }
        }
        // smem reuse across iterations is ordered by BAR A of the next pass
    }
}

// ---------------------------------------------------------------------------
// K3: out = out / (den + 1e-16) + skip
// ---------------------------------------------------------------------------
__global__ void final_kernel(float* __restrict__ out, int n) {
    int i = blockIdx.x * blockDim.x + threadIdx.x;
    if (i >= n * HC) return;
    const int row  = i >> 7;
    const int head = (i >> 6) & 1;
    out[i] = out[i] / (g_den[row * 2 + head] + 1e-16f) + g_sk[i];
}

// ---------------------------------------------------------------------------
extern "C" void kernel_launch(void* const* d_in, const int* in_sizes, int n_in,
                              void* d_out, int out_size)
{
    const float* x   = (const float*)d_in[0];
    const int*   ei  = (const int*)d_in[1];
    const int*   et  = (const int*)d_in[2];
    const float* msg = (const float*)d_in[3];
    const float* Wt  = (const float*)d_in[4];
    const float* bt  = (const float*)d_in[5];
    const float* Wq  = (const float*)d_in[6];
    const float* bq  = (const float*)d_in[7];
    const float* Wk  = (const float*)d_in[8];
    const float* bk  = (const float*)d_in[9];
    const float* Wv  = (const float*)d_in[10];
    const float* bv  = (const float*)d_in[11];
    const float* We  = (const float*)d_in[12];
    const float* Ws  = (const float*)d_in[13];
    const float* bs  = (const float*)d_in[14];
    float* out = (float*)d_out;

    const int N = in_sizes[0] / D;
    const int E = in_sizes[2];

    init_kernel<<<(N * HC + 255) / 256, 256>>>(out, N);
    proj_kernel<<<(N + 15) / 16, 128>>>(x, Wq, bq, Wk, bk, Wv, bv, Ws, bs, N);
    edge_kernel<<<444, 128>>>(ei, et, msg, Wt, bt, We, out, E);
    final_kernel<<<(N * HC + 255) / 256, 256>>>(out, N);
}